// round 9
// baseline (speedup 1.0000x reference)
#include <cuda_runtime.h>
#include <cstddef>

#define BATCH 8
#define LFRM  64
#define CH    3
#define HH    224
#define WW    224
#define HWSZ  (HH*WW)            // 50176
#define FRAMES (BATCH*LFRM)      // 512
#define PAIRS  (BATCH*(LFRM-1))  // 504
#define MSEL   16
#define EPSF   1e-6f

// ---------------- scratch (static device globals; no allocation) -------------
__device__ double g_ds2[PAIRS * 2];             // per-(pair,half) partial diff scores
__device__ int    g_idx[BATCH * MSEL];          // selected frame indices

// ============================================================================
// kernel 1: fused channel-sum + 7x7 box + pairwise |w0*box + eps| reduction
//
// y_l - y_{l+1} = w0 * box7x7( sum_c (x_l - x_{l+1}) )   (uniform w, bias cancels)
//
// grid (2, PAIRS): x = half (rows 0..111 / 112..223), y = pair index.
// 224 threads; thread t owns output column t.
// Horizontal 7-tap via smem row buffers; vertical 7-tap via register ring
// (fresh 7-term sum per output row -> no accumulation drift).
// ============================================================================
__global__ __launch_bounds__(224) void pairdiff_kernel(const float* __restrict__ x,
                                                       const float* __restrict__ wgt)
{
    __shared__ __align__(16) float buf[2][4][232];   // double-banked 4-row groups
    __shared__ double sd[224];

    const int t    = threadIdx.x;                    // 0..223
    const int half = blockIdx.x;                     // 0..1
    const int p    = blockIdx.y;                     // 0..503
    const int b    = p / (LFRM - 1);
    const int l    = p - b * (LFRM - 1);
    const int r0   = half * 112;

    const float w0 = __ldg(wgt);                     // uniform conv weight
    const float* xl = x + (size_t)(b * LFRM + l) * (CH * HWSZ);
    const float* xr = xl + (size_t)(CH * HWSZ);      // next frame

    // zero halo columns (positions 0..2, 227..229) of all 8 row buffers
    if (t < 6) {
        const int pc = (t < 3) ? t : 224 + t;        // 0,1,2,227,228,229
        for (int bk = 0; bk < 2; bk++)
            for (int e = 0; e < 4; e++) buf[bk][e][pc] = 0.f;
    }
    __syncthreads();

    float  hb[8];                                    // hbox register ring
#pragma unroll
    for (int k = 0; k < 8; k++) hb[k] = 0.f;
    double acc0 = 0.0, acc1 = 0.0;

    // input rows i = r0 - 3 + j, j = 0..119 (15 packs of 8 = 2 banked groups of 4)
#pragma unroll 1
    for (int pk = 0; pk < 15; pk++) {
#pragma unroll
        for (int bk = 0; bk < 2; bk++) {
            // ---- load 4 channel-summed difference rows into this bank ----
#pragma unroll
            for (int e = 0; e < 4; e++) {
                const int j = pk * 8 + bk * 4 + e;
                const int i = r0 - 3 + j;
                float d = 0.f;
                if ((unsigned)i < (unsigned)HH) {
                    const size_t off = (size_t)i * WW + t;
                    float a0 = __ldg(xl + off);
                    float a1 = __ldg(xl + HWSZ + off);
                    float a2 = __ldg(xl + 2 * HWSZ + off);
                    float b0 = __ldg(xr + off);
                    float b1 = __ldg(xr + HWSZ + off);
                    float b2 = __ldg(xr + 2 * HWSZ + off);
                    d = (a0 + a1 + a2) - (b0 + b1 + b2);
                }
                buf[bk][e][3 + t] = d;
            }
            __syncthreads();

            // ---- horizontal 7-tap box into ring, then emit output rows ----
#pragma unroll
            for (int e = 0; e < 4; e++) {
                const int j  = pk * 8 + bk * 4 + e;
                const int re = bk * 4 + e;           // ring slot (static)
                const float* rp = &buf[bk][e][t];    // covers cols t-3..t+3
                hb[re] = ((rp[0] + rp[1]) + (rp[2] + rp[3]))
                       + ((rp[4] + rp[5]) + rp[6]);

                if (j >= 6 && j <= 117) {            // output row r = r0 + j - 6
                    float vs = ((hb[(re)     & 7] + hb[(re + 7) & 7])
                             +  (hb[(re + 6) & 7] + hb[(re + 5) & 7]))
                             + ((hb[(re + 4) & 7] + hb[(re + 3) & 7])
                             +   hb[(re + 2) & 7]);
                    float pix = fabsf(fmaf(w0, vs, EPSF));
                    if (j & 1) acc1 += (double)pix;
                    else       acc0 += (double)pix;
                }
            }
            __syncthreads();   // all reads of this bank done before next reuse
        }
    }

    // ---- block reduction of double partials ----
    sd[t] = acc0 + acc1;
    __syncthreads();
    if (t < 112) sd[t] += sd[t + 112];
    __syncthreads();
    if (t < 56)  sd[t] += sd[t + 56];
    __syncthreads();
    if (t < 28)  sd[t] += sd[t + 28];
    __syncthreads();
    if (t < 14)  sd[t] += sd[t + 14];
    __syncthreads();
    if (t < 7)   sd[t] += sd[t + 7];
    __syncthreads();
    if (t == 0) {
        double s = sd[0];
        for (int k = 1; k < 7; k++) s += sd[k];
        g_ds2[p * 2 + half] = s;
    }
}

// ---------------- kernel 2: sqrt / normalize / cumsum / argmin ---------------
// ratio = 16/64 = 0.25 ; exponent = sqrt(0.25) = 0.5 -> dsp = sqrt(diff_score)
__global__ void select_kernel()
{
    const int b = threadIdx.x;
    if (b >= BATCH) return;

    double dsp[LFRM - 1];
    double s = 0.0;
    for (int l = 0; l < LFRM - 1; l++) {
        const int p = b * (LFRM - 1) + l;
        double d = sqrt(g_ds2[p * 2] + g_ds2[p * 2 + 1]);
        dsp[l] = d;
        s += d;
    }
    double cums[LFRM - 1];
    double c = 0.0;
    for (int l = 0; l < LFRM - 1; l++) {
        c += dsp[l] / s;
        cums[l] = c;
    }
    const float interval = 1.0f / (float)(MSEL - 1);
    for (int m = 0; m < MSEL; m++) {
        double target = (double)((float)m * interval);
        double best = 1e300;
        int bi = 0;
        for (int l = 0; l < LFRM - 1; l++) {
            double d = fabs(cums[l] - target);
            if (d < best) { best = d; bi = l; }   // strict '<' => first occurrence
        }
        g_idx[b * MSEL + m] = bi;
    }
}

// ---------------- kernel 3: gather selected frames ---------------------------
__global__ __launch_bounds__(256) void gather_kernel(const float* __restrict__ x,
                                                     float* __restrict__ out)
{
    const int bm = blockIdx.y;             // 0..127
    const int b  = bm >> 4;
    const int src = b * LFRM + g_idx[bm];
    const float4* sp = (const float4*)(x + (size_t)src * (CH * HWSZ));
    float4* dp = (float4*)(out + (size_t)bm * (CH * HWSZ));
    const int i = blockIdx.x * 256 + threadIdx.x;   // 147*256 = 37632 exact
    dp[i] = sp[i];
}

// ---------------- launcher ---------------------------------------------------
extern "C" void kernel_launch(void* const* d_in, const int* in_sizes, int n_in,
                              void* d_out, int out_size)
{
    const float* x = nullptr;
    const float* w = nullptr;
    for (int i = 0; i < n_in; i++) {
        if (in_sizes[i] == FRAMES * CH * HWSZ) x = (const float*)d_in[i];
        else if (in_sizes[i] == CH * 49)       w = (const float*)d_in[i];
    }

    pairdiff_kernel<<<dim3(2, PAIRS), 224>>>(x, w);
    select_kernel<<<1, 32>>>();
    gather_kernel<<<dim3(147, BATCH * MSEL), 256>>>(x, (float*)d_out);
}

// round 10
// speedup vs baseline: 2.1815x; 2.1815x over previous
#include <cuda_runtime.h>
#include <cstddef>

#define BATCH 8
#define LFRM  64
#define CH    3
#define HH    224
#define WW    224
#define HWSZ  (HH*WW)            // 50176
#define FRAMES (BATCH*LFRM)      // 512
#define PAIRS  (BATCH*(LFRM-1))  // 504
#define MSEL   16
#define EPSF   1e-6f

#define NCHUNK 4                 // row chunks per pair
#define CROWS  56                // output rows per chunk (4*56 = 224)
#define INROWS 62                // input rows needed: 56 + 6 halo

// ---------------- scratch (static device globals; no allocation) -------------
__device__ double g_ds4[PAIRS * NCHUNK];        // per-(pair,chunk) partial diff scores
__device__ int    g_idx[BATCH * MSEL];          // selected frame indices

// ============================================================================
// kernel 1: fused channel-sum + 7x7 box + pairwise |w0*box + eps| reduction
//
// y_l - y_{l+1} = w0 * box7x7( sum_c (x_l - x_{l+1}) )   (uniform w, bias cancels)
//
// grid (NCHUNK, PAIRS): x = row chunk (56 output rows), y = pair index.
// 224 threads; thread t owns output column t.
// Horizontal 7-tap via smem row buffers; vertical 7-tap via register ring
// (fresh 7-term sum per output row -> no accumulation drift).
// ============================================================================
__global__ __launch_bounds__(224) void pairdiff_kernel(const float* __restrict__ x,
                                                       const float* __restrict__ wgt)
{
    __shared__ __align__(16) float buf[2][4][232];   // double-banked 4-row groups
    __shared__ double sd[224];

    const int t     = threadIdx.x;                   // 0..223
    const int chunk = blockIdx.x;                    // 0..3
    const int p     = blockIdx.y;                    // 0..503
    const int b     = p / (LFRM - 1);
    const int l     = p - b * (LFRM - 1);
    const int r0    = chunk * CROWS;

    const float w0 = __ldg(wgt);                     // uniform conv weight
    const float* xl = x + (size_t)(b * LFRM + l) * (CH * HWSZ);
    const float* xr = xl + (size_t)(CH * HWSZ);      // next frame

    // zero halo columns (positions 0..2, 227..229) of all 8 row buffers
    if (t < 6) {
        const int pc = (t < 3) ? t : 224 + t;        // 0,1,2,227,228,229
        for (int bk = 0; bk < 2; bk++)
            for (int e = 0; e < 4; e++) buf[bk][e][pc] = 0.f;
    }
    __syncthreads();

    float  hb[8];                                    // hbox register ring
#pragma unroll
    for (int k = 0; k < 8; k++) hb[k] = 0.f;
    double acc0 = 0.0, acc1 = 0.0;

    // input rows i = r0 - 3 + j, j = 0..61 (8 packs of 8; last rows wasted)
#pragma unroll 1
    for (int pk = 0; pk < 8; pk++) {
#pragma unroll
        for (int bk = 0; bk < 2; bk++) {
            // ---- load 4 channel-summed difference rows into this bank ----
#pragma unroll
            for (int e = 0; e < 4; e++) {
                const int j = pk * 8 + bk * 4 + e;
                const int i = r0 - 3 + j;
                float d = 0.f;
                if ((unsigned)i < (unsigned)HH && j < INROWS) {
                    const size_t off = (size_t)i * WW + t;
                    float a0 = __ldg(xl + off);
                    float a1 = __ldg(xl + HWSZ + off);
                    float a2 = __ldg(xl + 2 * HWSZ + off);
                    float b0 = __ldg(xr + off);
                    float b1 = __ldg(xr + HWSZ + off);
                    float b2 = __ldg(xr + 2 * HWSZ + off);
                    d = (a0 + a1 + a2) - (b0 + b1 + b2);
                }
                buf[bk][e][3 + t] = d;
            }
            __syncthreads();

            // ---- horizontal 7-tap box into ring, then emit output rows ----
#pragma unroll
            for (int e = 0; e < 4; e++) {
                const int j  = pk * 8 + bk * 4 + e;
                const int re = bk * 4 + e;           // ring slot (static)
                const float* rp = &buf[bk][e][t];    // covers cols t-3..t+3
                hb[re] = ((rp[0] + rp[1]) + (rp[2] + rp[3]))
                       + ((rp[4] + rp[5]) + rp[6]);

                if (j >= 6 && j < 6 + CROWS) {       // output row r = r0 + j - 6
                    float vs = ((hb[(re)     & 7] + hb[(re + 7) & 7])
                             +  (hb[(re + 6) & 7] + hb[(re + 5) & 7]))
                             + ((hb[(re + 4) & 7] + hb[(re + 3) & 7])
                             +   hb[(re + 2) & 7]);
                    float pix = fabsf(fmaf(w0, vs, EPSF));
                    if (j & 1) acc1 += (double)pix;
                    else       acc0 += (double)pix;
                }
            }
            __syncthreads();   // all reads of this bank done before next reuse
        }
    }

    // ---- block reduction of double partials ----
    sd[t] = acc0 + acc1;
    __syncthreads();
    if (t < 112) sd[t] += sd[t + 112];
    __syncthreads();
    if (t < 56)  sd[t] += sd[t + 56];
    __syncthreads();
    if (t < 28)  sd[t] += sd[t + 28];
    __syncthreads();
    if (t < 14)  sd[t] += sd[t + 14];
    __syncthreads();
    if (t < 7)   sd[t] += sd[t + 7];
    __syncthreads();
    if (t == 0) {
        double s = sd[0];
        for (int k = 1; k < 7; k++) s += sd[k];
        g_ds4[p * NCHUNK + chunk] = s;
    }
}

// ---------------- kernel 2: sqrt / normalize / cumsum / argmin (parallel) ----
// ratio = 16/64 = 0.25 ; exponent = sqrt(0.25) = 0.5 -> dsp = sqrt(diff_score)
__global__ __launch_bounds__(512) void select_kernel()
{
    __shared__ double dsp[PAIRS];
    __shared__ double cum[PAIRS];
    const int t = threadIdx.x;

    // parallel sqrts (one per pair)
    if (t < PAIRS) {
        const double* q = &g_ds4[t * NCHUNK];
        dsp[t] = sqrt((q[0] + q[1]) + (q[2] + q[3]));
    }
    __syncthreads();

    // per-batch sum + cumsum (8 short serial chains in one warp)
    if (t < BATCH) {
        const double* dp = &dsp[t * (LFRM - 1)];
        double s = 0.0;
        for (int l = 0; l < LFRM - 1; l++) s += dp[l];
        const double inv = 1.0 / s;
        double c = 0.0;
        for (int l = 0; l < LFRM - 1; l++) {
            c += dp[l] * inv;
            cum[t * (LFRM - 1) + l] = c;
        }
    }
    __syncthreads();

    // parallel argmin: one thread per (batch, sample)
    if (t < BATCH * MSEL) {
        const int b = t >> 4, m = t & 15;
        const double* cp = &cum[b * (LFRM - 1)];
        const float interval = 1.0f / (float)(MSEL - 1);
        const double target = (double)((float)m * interval);
        double best = 1e300;
        int bi = 0;
        for (int l = 0; l < LFRM - 1; l++) {
            double d = fabs(cp[l] - target);
            if (d < best) { best = d; bi = l; }   // strict '<' => first occurrence
        }
        g_idx[t] = bi;
    }
}

// ---------------- kernel 3: gather selected frames ---------------------------
__global__ __launch_bounds__(256) void gather_kernel(const float* __restrict__ x,
                                                     float* __restrict__ out)
{
    const int bm = blockIdx.y;             // 0..127
    const int b  = bm >> 4;
    const int src = b * LFRM + g_idx[bm];
    const float4* sp = (const float4*)(x + (size_t)src * (CH * HWSZ));
    float4* dp = (float4*)(out + (size_t)bm * (CH * HWSZ));
    const int i = blockIdx.x * 256 + threadIdx.x;   // 147*256 = 37632 exact
    dp[i] = sp[i];
}

// ---------------- launcher ---------------------------------------------------
extern "C" void kernel_launch(void* const* d_in, const int* in_sizes, int n_in,
                              void* d_out, int out_size)
{
    const float* x = nullptr;
    const float* w = nullptr;
    for (int i = 0; i < n_in; i++) {
        if (in_sizes[i] == FRAMES * CH * HWSZ) x = (const float*)d_in[i];
        else if (in_sizes[i] == CH * 49)       w = (const float*)d_in[i];
    }

    pairdiff_kernel<<<dim3(NCHUNK, PAIRS), 224>>>(x, w);
    select_kernel<<<1, 512>>>();
    gather_kernel<<<dim3(147, BATCH * MSEL), 256>>>(x, (float*)d_out);
}